// round 14
// baseline (speedup 1.0000x reference)
#include <cuda_runtime.h>
#include <math.h>

// SpectralConv1d_plus: B=32, N=16384, C_in=C_out=32, MODES=512, conv width 5.
// Pruned transform with internal FFTs:
//   N = 512*32; f = r + 32j (r<32, j<16), n = q + 512p, q = c + 32d (c<32, d<16).
// forward:  per-lane (lane=q) real-input 32-pt FFT over p (fft16 + Hermitian
//           untangle), N-twiddle via 4 independent rotator chains, 16-pt FFT
//           over d, combine over c.
// inverse (transpose): 16-pt inv FFT + 2-chain rotator + 32-pt DIT synthesis.
// All normalizations fold into (f==0 ? 1 : 2)/N applied in k_conv.
// R13 lesson: k_fwd latency-bound (no pipe >56%); this round splits the
// serial rotator chains (4x fwd, 2x inv), splits phase-3 accumulators, and
// swaps g_Xf/g_G layouts so the scattered global stores become coalesced.

#define NFFT   16384
#define MODES  512
#define FCONV  508

__device__ float2 g_tw[NFFT];                   // e^{+2pi i k/N}
__device__ float  g_xt[32 * 32 * NFFT];         // [b][c][n]
__device__ float2 g_Xf[32 * 32 * MODES];        // [b][i][f]   (R14: was [b][f][i])
__device__ float2 g_Wt[MODES * 32 * 32];        // [f][i][o]
__device__ float2 g_Y1[32 * MODES * 32];        // [b][f][o]
__device__ float2 g_G [32 * MODES * 32];        // [b][f][o]   (R14: was [b][o][f])
__device__ float  g_yt[32 * 32 * NFFT];         // [b][o][n]

#define SMEM_FWD  ((512 * 33 * 2 + 1024) * 4)                 // 139264 B
#define SMEM_INV  ((512 * 33 * 2 + 1056 + 1024 + 64) * 4)     // 143744 B
#define SMEM_CONV ((68 * 32 * 2 + 2 * 5120) * 4)              // 58368 B

// ---------------- 16-point complex FFT, fully in registers -----------------
// Computes V[j] = sum_d v[d] e^{SGN*2pi i jd/16}, natural order in/out.
template<int SGN>
__device__ __forceinline__ void fft16(float vr[16], float vi[16]) {
#define SWP(a,b) { float t_=vr[a]; vr[a]=vr[b]; vr[b]=t_; \
                   t_=vi[a]; vi[a]=vi[b]; vi[b]=t_; }
    SWP(1,8) SWP(2,4) SWP(3,12) SWP(5,10) SWP(7,14) SWP(11,13)
#undef SWP
#define BFLY(i0,i1,wr,wi) { \
    const float wr_ = (wr), wi_ = (float)SGN * (wi); \
    float tr_ = wr_*vr[i1] - wi_*vi[i1]; \
    float ti_ = wr_*vi[i1] + wi_*vr[i1]; \
    vr[i1] = vr[i0] - tr_; vi[i1] = vi[i0] - ti_; \
    vr[i0] += tr_;         vi[i0] += ti_; }
    // len=2
    BFLY(0,1,1.f,0.f)  BFLY(2,3,1.f,0.f)  BFLY(4,5,1.f,0.f)  BFLY(6,7,1.f,0.f)
    BFLY(8,9,1.f,0.f)  BFLY(10,11,1.f,0.f) BFLY(12,13,1.f,0.f) BFLY(14,15,1.f,0.f)
    // len=4: w = 1, (0,SGN)
    BFLY(0,2,1.f,0.f)  BFLY(1,3,0.f,1.f)
    BFLY(4,6,1.f,0.f)  BFLY(5,7,0.f,1.f)
    BFLY(8,10,1.f,0.f) BFLY(9,11,0.f,1.f)
    BFLY(12,14,1.f,0.f) BFLY(13,15,0.f,1.f)
    // len=8: w = e^{SGN 2pi i k/8}, k=0..3
    {
        const float C8 = 0.70710678118654752f;
        BFLY(0,4,1.f,0.f)  BFLY(1,5,C8,C8)  BFLY(2,6,0.f,1.f)  BFLY(3,7,-C8,C8)
        BFLY(8,12,1.f,0.f) BFLY(9,13,C8,C8) BFLY(10,14,0.f,1.f) BFLY(11,15,-C8,C8)
    }
    // len=16: w = e^{SGN 2pi i k/16}, k=0..7
    {
        const float C8 = 0.70710678118654752f;
        const float CA = 0.92387953251128674f, SA = 0.38268343236508977f;
        BFLY(0,8,1.f,0.f)   BFLY(1,9,CA,SA)    BFLY(2,10,C8,C8)  BFLY(3,11,SA,CA)
        BFLY(4,12,0.f,1.f)  BFLY(5,13,-SA,CA)  BFLY(6,14,-C8,C8) BFLY(7,15,-CA,SA)
    }
#undef BFLY
}

// --------------------------------- init -----------------------------------
__global__ void k_init() {
    int k = blockIdx.x * blockDim.x + threadIdx.x;   // 64*256 = 16384
    float s, c;
    sincospif((float)k / 8192.0f, &s, &c);           // angle = 2*pi*k/N
    g_tw[k] = make_float2(c, s);
}

// x [B,N,C] -> g_xt [B,C,N]
__global__ void k_tin(const float* __restrict__ x) {
    __shared__ float t[32][33];
    int tx = threadIdx.x, ty = threadIdx.y;
    int n0 = blockIdx.x * 32, b = blockIdx.y;
#pragma unroll
    for (int k = 0; k < 4; k++) {
        int row = ty + k * 8;
        t[row][tx] = x[((size_t)b * NFFT + n0 + row) * 32 + tx];
    }
    __syncthreads();
#pragma unroll
    for (int k = 0; k < 4; k++) {
        int c = ty + k * 8;
        g_xt[((size_t)b * 32 + c) * NFFT + n0 + tx] = t[tx][c];
    }
}

// w_real/w_imag [i][o][f] -> g_Wt[f][i*32+o] float2
__global__ void k_wt(const float* __restrict__ wr, const float* __restrict__ wi) {
    __shared__ float tr[32][33], ti[32][33];
    int tx = threadIdx.x, ty = threadIdx.y;
    int f0 = blockIdx.x * 32, io0 = blockIdx.y * 32;
#pragma unroll
    for (int k = 0; k < 4; k++) {
        int row = ty + k * 8;
        tr[row][tx] = wr[(io0 + row) * MODES + f0 + tx];
        ti[row][tx] = wi[(io0 + row) * MODES + f0 + tx];
    }
    __syncthreads();
#pragma unroll
    for (int k = 0; k < 4; k++) {
        int fr = ty + k * 8;
        g_Wt[(f0 + fr) * 1024 + io0 + tx] = make_float2(tr[tx][fr], ti[tx][fr]);
    }
}

// ------------------------------ forward DFT --------------------------------
// One block per signal (b*32+i). 512 threads / 16 warps, 1 CTA/SM.
__global__ __launch_bounds__(512, 1) void k_fwd() {
    extern __shared__ float smem[];
    float*  Bre  = smem;                   // [q][r] padded: 512*33  (67.6 KB)
    float*  Bim  = Bre + 512 * 33;         // [q][r] padded: 512*33  (67.6 KB)
    float2* w512 = (float2*)(Bim + 512 * 33);  // e^{-2pi i t/512}   (4 KB)

    int sig = blockIdx.x;
    int tid = threadIdx.x, lane = tid & 31, w = tid >> 5;

    {
        float2 e = g_tw[(tid << 5) & (NFFT - 1)];
        w512[tid] = make_float2(e.x, -e.y);
    }
    __syncthreads();

    const float* xg = g_xt + (size_t)sig * NFFT;

    // ---- phase 1 (lane = q): real-input 32-pt FFT over p + N-twiddle -> Bre/Bim
    {
        const float W32R[16] = {
            1.f,                    0.98078528040323044913f, 0.92387953251128675613f,
            0.83146961230254523708f, 0.70710678118654752440f, 0.55557023301960222474f,
            0.38268343236508977173f, 0.19509032201612826785f, 0.f,
            -0.19509032201612826785f, -0.38268343236508977173f, -0.55557023301960222474f,
            -0.70710678118654752440f, -0.83146961230254523708f, -0.92387953251128675613f,
            -0.98078528040323044913f };
        const float W32I[16] = {
            0.f,                    0.19509032201612826785f, 0.38268343236508977173f,
            0.55557023301960222474f, 0.70710678118654752440f, 0.83146961230254523708f,
            0.92387953251128675613f, 0.98078528040323044913f, 1.f,
            0.98078528040323044913f, 0.92387953251128675613f, 0.83146961230254523708f,
            0.70710678118654752440f, 0.55557023301960222474f, 0.38268343236508977173f,
            0.19509032201612826785f };
        int q = (w << 5) + lane;
        const float* xq = xg + q;
        float zr[16], zi[16];
#pragma unroll
        for (int t = 0; t < 16; t++) {            // coalesced LDG.32 loads
            zr[t] = xq[t << 10];                  // x[q + 512*(2t)]
            zi[t] = xq[(t << 10) + 512];          // x[q + 512*(2t+1)]
        }
        fft16<-1>(zr, zi);                        // Z[k] = sum_t z e^{-2pi i kt/16}
        // Hermitian untangle: X[k] = Ze[k] + e^{-2pi i k/32} Zo[k], k=0..16
        float Xr[17], Xi[17];
#pragma unroll
        for (int k = 0; k < 16; k++) {
            int m = (16 - k) & 15;
            float Zer = 0.5f * (zr[k] + zr[m]);
            float Zei = 0.5f * (zi[k] - zi[m]);
            float Zor = 0.5f * (zi[k] + zi[m]);
            float Zoi = -0.5f * (zr[k] - zr[m]);
            Xr[k] = Zer + W32R[k] * Zor + W32I[k] * Zoi;
            Xi[k] = Zei + W32R[k] * Zoi - W32I[k] * Zor;
        }
        Xr[16] = zr[0] - zi[0];
        Xi[16] = 0.f;
        // B[r][q] = A[r] e^{-2pi i r q/N}; A[r>16] = conj(A[32-r]).
        // 4 independent rotator chains: chain k starts at ed^k, steps ed^4.
        float2 ed = g_tw[q];
        float dc = ed.x, ds = -ed.y;              // ed = e^{-2pi i q/N}
        float d2c = dc * dc - ds * ds, d2s = 2.f * dc * ds;
        float d4c = d2c * d2c - d2s * d2s, d4s = 2.f * d2c * d2s;
        float rc[4], rs[4];
        rc[0] = 1.f;  rs[0] = 0.f;
        rc[1] = dc;   rs[1] = ds;
        rc[2] = d2c;  rs[2] = d2s;
        rc[3] = d2c * dc - d2s * ds;  rs[3] = d2c * ds + d2s * dc;
        int q33 = q * 33;
#pragma unroll
        for (int rr = 0; rr < 8; rr++) {
#pragma unroll
            for (int k4 = 0; k4 < 4; k4++) {
                int r = rr * 4 + k4;
                float Ar = (r <= 16) ? Xr[r] : Xr[32 - r];
                float Ai = (r <= 16) ? Xi[r] : -Xi[32 - r];
                Bre[q33 + r] = Ar * rc[k4] - Ai * rs[k4];   // stride-33: conflict-free
                Bim[q33 + r] = Ar * rs[k4] + Ai * rc[k4];
            }
#pragma unroll
            for (int k4 = 0; k4 < 4; k4++) {
                float nc = rc[k4] * d4c - rs[k4] * d4s;
                float ns = rc[k4] * d4s + rs[k4] * d4c;
                rc[k4] = nc; rs[k4] = ns;
            }
        }
    }
    __syncthreads();

    // ---- phase 2: 16-pt FFT over d (q = c + 32d), in place, per (c, r=lane)
    for (int tt = 0; tt < 2; tt++) {
        int c = w + tt * 16;
        float vr[16], vi[16];
#pragma unroll
        for (int d = 0; d < 16; d++) {
            int idx = (c + (d << 5)) * 33 + lane;
            vr[d] = Bre[idx]; vi[d] = Bim[idx];
        }
        fft16<-1>(vr, vi);
#pragma unroll
        for (int j = 0; j < 16; j++) {
            int idx = (c + (j << 5)) * 33 + lane;
            Bre[idx] = vr[j]; Bim[idx] = vi[j];
        }
    }
    __syncthreads();

    // ---- phase 3: combine over c. warp w -> j = w, lane = r. Dual accumulators.
    {
        int j = w;
        float xr0 = 0.f, xi0 = 0.f, xr1 = 0.f, xi1 = 0.f;
#pragma unroll 8
        for (int c = 0; c < 32; c += 2) {
            int idx0 = (c + (j << 5)) * 33 + lane;
            float br0 = Bre[idx0], bi0 = Bim[idx0];
            float2 wv0 = w512[(j * c) & 511];              // broadcast
            xr0 += br0 * wv0.x - bi0 * wv0.y;
            xi0 += br0 * wv0.y + bi0 * wv0.x;
            int idx1 = (c + 1 + (j << 5)) * 33 + lane;
            float br1 = Bre[idx1], bi1 = Bim[idx1];
            float2 wv1 = w512[(j * (c + 1)) & 511];        // broadcast
            xr1 += br1 * wv1.x - bi1 * wv1.y;
            xi1 += br1 * wv1.y + bi1 * wv1.x;
        }
        // [b][i][f] layout: lane-consecutive f -> coalesced warp store
        g_Xf[(size_t)sig * MODES + lane + (j << 5)] = make_float2(xr0 + xr1, xi0 + xi1);
    }
}

// ------------------------------ channel mix --------------------------------
__global__ void k_einsum() {
    __shared__ float2 Xs[1024];   // [b][i]
    __shared__ float2 Wsm[1024];  // [i][o]
    int f = blockIdx.x, tid = threadIdx.x;
    for (int k = tid; k < 1024; k += 256) {
        Wsm[k] = g_Wt[f * 1024 + k];
        // g_Xf is [b][i][f]: strided read, 4 MB L2-resident
        Xs[k] = g_Xf[(size_t)k * MODES + f];
    }
    __syncthreads();
    int o = tid & 31, bg = tid >> 5;
    for (int bb = bg; bb < 32; bb += 8) {
        float yr = 0.f, yi = 0.f;
#pragma unroll
        for (int ii = 0; ii < 32; ii++) {
            float2 xv = Xs[bb * 32 + ii];
            float2 wv = Wsm[ii * 32 + o];
            yr += xv.x * wv.x - xv.y * wv.y;
            yi += xv.x * wv.y + xv.y * wv.x;
        }
        g_Y1[((size_t)bb * MODES + f) * 32 + o] = make_float2(yr, yi);
    }
}

// ----------------------------- frequency conv ------------------------------
__global__ void k_conv(const float* __restrict__ kre, const float* __restrict__ kim) {
    extern __shared__ float cs[];
    float2* Ys  = (float2*)cs;            // 68*32
    float*  krs = cs + 68 * 32 * 2;       // 5120
    float*  kis = krs + 5120;             // 5120
    int tx = threadIdx.x, ty = threadIdx.y;
    int tid = ty * 32 + tx;
    int b = blockIdx.y, f0 = blockIdx.x * 64;
    int nrows = min(68, 512 - f0);
    for (int k = tid; k < nrows * 32; k += 256)
        Ys[k] = g_Y1[((size_t)b * MODES + f0) * 32 + k];
    for (int k = tid; k < 5120; k += 256) { krs[k] = kre[k]; kis[k] = kim[k]; }
    __syncthreads();
    for (int c8 = 0; c8 < 8; c8++) {
        int fl = ty * 8 + c8;
        int f = f0 + fl;
        float gr = 0.f, gi = 0.f;
        if (f < FCONV) {
#pragma unroll
            for (int w5 = 0; w5 < 5; w5++)
#pragma unroll
                for (int c = 0; c < 32; c++) {
                    float2 yv = Ys[(fl + w5) * 32 + c];
                    gr += yv.x * krs[(w5 * 32 + c) * 32 + tx];
                    gi += yv.y * kis[(w5 * 32 + c) * 32 + tx];
                }
            float sc = (f == 0) ? (1.0f / NFFT) : (2.0f / NFFT);
            gr *= sc; gi *= sc;
        }
        // [b][f][o] layout: lane-consecutive o -> coalesced warp store
        g_G[((size_t)b * MODES + f) * 32 + tx] = make_float2(gr, gi);
    }
}

// ------------------------------ inverse DFT --------------------------------
// One block per signal. 512 threads, 1 CTA/SM.
__global__ __launch_bounds__(512, 1) void k_inv() {
    extern __shared__ float smem[];
    float*  Dre   = smem;                        // [512][33]
    float*  Dim   = Dre + 512 * 33;              // [512][33]
    float2* Gs    = (float2*)(Dim + 512 * 33);   // [j][33] padded (528)
    float2* w512p = Gs + 528;                    // e^{+2pi i t/512}
    float2* cs32  = w512p + 512;                 // (kept for layout)

    int sig = blockIdx.x;
    int b   = sig >> 5, o = sig & 31;
    int tid = threadIdx.x, lane = tid & 31, w = tid >> 5;

    w512p[tid] = g_tw[(tid << 5) & (NFFT - 1)];
    if (tid < 32) cs32[tid] = g_tw[tid << 9];
    {   // G [b][f][o] -> smem [j][r] padded; f = tid: r = tid&31, j = tid>>5
        float2 gv = g_G[((size_t)b * MODES + tid) * 32 + o];
        Gs[(tid >> 5) * 33 + (tid & 31)] = gv;
    }
    __syncthreads();

    // ---- phase A: per task (c, r=lane): twiddle + 16-pt inverse FFT + N-twiddle
    for (int tt = 0; tt < 2; tt++) {
        int c = w + tt * 16;
        float vr[16], vi[16];
#pragma unroll
        for (int j = 0; j < 16; j++) {
            float2 gv = Gs[j * 33 + lane];
            float2 wv = w512p[(j * c) & 511];          // broadcast
            vr[j] = gv.x * wv.x - gv.y * wv.y;
            vi[j] = gv.x * wv.y + gv.y * wv.x;
        }
        fft16<+1>(vr, vi);                              // j -> d
        // N-twiddle via 2 independent rotator chains (step st^2)
        float2 t0 = g_tw[(lane * c) & (NFFT - 1)];      // e^{+2pi i r c/N}
        float2 st = w512p[lane];                        // e^{+2pi i r/512}
        float s2c = st.x * st.x - st.y * st.y, s2s = 2.f * st.x * st.y;
        float tc0 = t0.x, ts0 = t0.y;
        float tc1 = t0.x * st.x - t0.y * st.y, ts1 = t0.x * st.y + t0.y * st.x;
#pragma unroll
        for (int d = 0; d < 16; d += 2) {
            int m0 = c + (d << 5);
            Dre[m0 * 33 + lane] = vr[d] * tc0 - vi[d] * ts0;
            Dim[m0 * 33 + lane] = vr[d] * ts0 + vi[d] * tc0;
            int m1 = c + ((d + 1) << 5);
            Dre[m1 * 33 + lane] = vr[d + 1] * tc1 - vi[d + 1] * ts1;
            Dim[m1 * 33 + lane] = vr[d + 1] * ts1 + vi[d + 1] * tc1;
            float n0c = tc0 * s2c - ts0 * s2s, n0s = tc0 * s2s + ts0 * s2c;
            tc0 = n0c; ts0 = n0s;
            float n1c = tc1 * s2c - ts1 * s2s, n1s = tc1 * s2s + ts1 * s2c;
            tc1 = n1c; ts1 = n1s;
        }
    }
    __syncthreads();

    // ---- phase B: 32-pt synthesis via 2x fft16 (DIT split).
    // y[s] = Re( sum_r D[r] e^{+2pi i r s/32} ):
    //   E = fft16(+1) of D[even r], O = fft16(+1) of D[odd r];
    //   y[k] = Er[k] + Re(w32^k O[k]); y[k+16] = Er[k] - Re(w32^k O[k]).
    {
        const float W32R[16] = {
            1.f,                    0.98078528040323044913f, 0.92387953251128675613f,
            0.83146961230254523708f, 0.70710678118654752440f, 0.55557023301960222474f,
            0.38268343236508977173f, 0.19509032201612826785f, 0.f,
            -0.19509032201612826785f, -0.38268343236508977173f, -0.55557023301960222474f,
            -0.70710678118654752440f, -0.83146961230254523708f, -0.92387953251128675613f,
            -0.98078528040323044913f };
        const float W32I[16] = {
            0.f,                    0.19509032201612826785f, 0.38268343236508977173f,
            0.55557023301960222474f, 0.70710678118654752440f, 0.83146961230254523708f,
            0.92387953251128675613f, 0.98078528040323044913f, 1.f,
            0.98078528040323044913f, 0.92387953251128675613f, 0.83146961230254523708f,
            0.70710678118654752440f, 0.55557023301960222474f, 0.38268343236508977173f,
            0.19509032201612826785f };
        float er[16], ei[16], odr[16], odi[16];
#pragma unroll
        for (int d = 0; d < 16; d++) {
            er[d]  = Dre[tid * 33 + 2 * d];     ei[d]  = Dim[tid * 33 + 2 * d];
            odr[d] = Dre[tid * 33 + 2 * d + 1]; odi[d] = Dim[tid * 33 + 2 * d + 1];
        }
        fft16<+1>(er, ei);
        fft16<+1>(odr, odi);
        float* yo = g_yt + (size_t)sig * NFFT + tid;   // m = tid; coalesced per s
#pragma unroll
        for (int k = 0; k < 16; k++) {
            float t = W32R[k] * odr[k] - W32I[k] * odi[k];
            yo[(size_t)k << 9]        = er[k] + t;
            yo[(size_t)(k + 16) << 9] = er[k] - t;
        }
    }
}

// g_yt [B,C,N] -> out [B,N,C]
__global__ void k_tout(float* __restrict__ out) {
    __shared__ float t[32][33];
    int tx = threadIdx.x, ty = threadIdx.y;
    int n0 = blockIdx.x * 32, b = blockIdx.y;
#pragma unroll
    for (int k = 0; k < 4; k++) {
        int c = ty + k * 8;
        t[c][tx] = g_yt[((size_t)b * 32 + c) * NFFT + n0 + tx];
    }
    __syncthreads();
#pragma unroll
    for (int k = 0; k < 4; k++) {
        int row = ty + k * 8;
        out[((size_t)b * NFFT + n0 + row) * 32 + tx] = t[tx][row];
    }
}

extern "C" void kernel_launch(void* const* d_in, const int* in_sizes, int n_in,
                              void* d_out, int out_size) {
    const float* x  = (const float*)d_in[0];
    const float* wr = (const float*)d_in[1];
    const float* wi = (const float*)d_in[2];
    const float* kr = (const float*)d_in[3];
    const float* ki = (const float*)d_in[4];
    float* out = (float*)d_out;

    cudaFuncSetAttribute(k_fwd,  cudaFuncAttributeMaxDynamicSharedMemorySize, SMEM_FWD);
    cudaFuncSetAttribute(k_inv,  cudaFuncAttributeMaxDynamicSharedMemorySize, SMEM_INV);
    cudaFuncSetAttribute(k_conv, cudaFuncAttributeMaxDynamicSharedMemorySize, SMEM_CONV);

    k_init<<<64, 256>>>();
    k_tin<<<dim3(NFFT / 32, 32), dim3(32, 8)>>>(x);
    k_wt<<<dim3(16, 32), dim3(32, 8)>>>(wr, wi);
    k_fwd<<<1024, 512, SMEM_FWD>>>();
    k_einsum<<<512, 256>>>();
    k_conv<<<dim3(8, 32), dim3(32, 8), SMEM_CONV>>>(kr, ki);
    k_inv<<<1024, 512, SMEM_INV>>>();
    k_tout<<<dim3(NFFT / 32, 32), dim3(32, 8)>>>(out);
}